// round 1
// baseline (speedup 1.0000x reference)
#include <cuda_runtime.h>

#define B_ 2
#define N_ 2048
#define D_ 2048
#define H_ 16
#define HD_ 128
#define CH_ 128
#define NC_ (N_/CH_)          // 16
#define QKVS_ (3*H_*HD_)      // 6144
#define LDP 132               // padded smem stride (132*4B = 528B, 16B aligned)

// ---------------- scratch (static device allocations only) ----------------
__device__ float g_qkv[(size_t)B_ * N_ * QKVS_];           // silu(x @ Wqkv^T)
__device__ float g_gate[(size_t)B_ * N_ * D_];             // sigmoid(x @ Wg^T), later y
__device__ float g_O[(size_t)B_ * N_ * D_];                // attention output [b,n,h*hd]
__device__ float g_A[(size_t)B_ * H_ * NC_ * HD_ * HD_];   // per-chunk KV contributions
__device__ float g_KV[(size_t)B_ * H_ * NC_ * HD_ * HD_];  // KV state at chunk starts

// ---------------- generic fp32 GEMM: C = act(A @ B^T) ----------------
// A: [M,K] row-major, B: [Nn,K] row-major, C: [M,Nn]
// act: 0=none, 1=silu, 2=sigmoid
__device__ __forceinline__ float act_apply(float v, int act) {
    if (act == 1) return v / (1.f + expf(-v));
    if (act == 2) return 1.f / (1.f + expf(-v));
    return v;
}

__global__ __launch_bounds__(256) void gemm_nt_act(
    const float* __restrict__ A, const float* __restrict__ Bm,
    float* __restrict__ C, int M, int Nn, int K, int act)
{
    __shared__ float As[16][LDP];
    __shared__ float Bs[16][LDP];
    const int tid = threadIdx.x;
    const int bm = blockIdx.y * 128;
    const int bn = blockIdx.x * 128;
    const int tx = tid & 15;
    const int ty = tid >> 4;
    const int r0 = tid >> 2;            // 0..63
    const int c4 = (tid & 3) << 2;      // 0,4,8,12

    float acc[8][8];
#pragma unroll
    for (int i = 0; i < 8; i++)
#pragma unroll
        for (int j = 0; j < 8; j++) acc[i][j] = 0.f;

    for (int k0 = 0; k0 < K; k0 += 16) {
        float4 a0 = *(const float4*)(A + (size_t)(bm + r0) * K + k0 + c4);
        float4 a1 = *(const float4*)(A + (size_t)(bm + r0 + 64) * K + k0 + c4);
        float4 b0 = *(const float4*)(Bm + (size_t)(bn + r0) * K + k0 + c4);
        float4 b1 = *(const float4*)(Bm + (size_t)(bn + r0 + 64) * K + k0 + c4);
        __syncthreads();
        As[c4+0][r0] = a0.x; As[c4+1][r0] = a0.y; As[c4+2][r0] = a0.z; As[c4+3][r0] = a0.w;
        As[c4+0][r0+64] = a1.x; As[c4+1][r0+64] = a1.y; As[c4+2][r0+64] = a1.z; As[c4+3][r0+64] = a1.w;
        Bs[c4+0][r0] = b0.x; Bs[c4+1][r0] = b0.y; Bs[c4+2][r0] = b0.z; Bs[c4+3][r0] = b0.w;
        Bs[c4+0][r0+64] = b1.x; Bs[c4+1][r0+64] = b1.y; Bs[c4+2][r0+64] = b1.z; Bs[c4+3][r0+64] = b1.w;
        __syncthreads();
#pragma unroll
        for (int kk = 0; kk < 16; kk++) {
            float a[8], b[8];
            *(float4*)&a[0] = *(const float4*)&As[kk][ty*8];
            *(float4*)&a[4] = *(const float4*)&As[kk][ty*8+4];
            *(float4*)&b[0] = *(const float4*)&Bs[kk][tx*8];
            *(float4*)&b[4] = *(const float4*)&Bs[kk][tx*8+4];
#pragma unroll
            for (int i = 0; i < 8; i++)
#pragma unroll
                for (int j = 0; j < 8; j++)
                    acc[i][j] = fmaf(a[i], b[j], acc[i][j]);
        }
    }

#pragma unroll
    for (int i = 0; i < 8; i++) {
        int row = bm + ty*8 + i;
        float* cp = C + (size_t)row * Nn + bn + tx*8;
        float4 o0, o1;
        o0.x = act_apply(acc[i][0], act); o0.y = act_apply(acc[i][1], act);
        o0.z = act_apply(acc[i][2], act); o0.w = act_apply(acc[i][3], act);
        o1.x = act_apply(acc[i][4], act); o1.y = act_apply(acc[i][5], act);
        o1.z = act_apply(acc[i][6], act); o1.w = act_apply(acc[i][7], act);
        *(float4*)cp = o0;
        *(float4*)(cp + 4) = o1;
    }
}

// ---------------- phase 1: per-chunk intra attention + KV summary ----------------
// For chunk c of head (b,h):
//   S[i][j] = (q_i . k_j) * lambda^(i-j)  (j<=i), O_intra = S V
//   A[e][d] = sum_j lambda^(127-j) k_j[e] v_j[d]
__global__ __launch_bounds__(256) void attn_phase1(const float* __restrict__ slope)
{
    extern __shared__ float sm[];
    float* Kt   = sm;                 // [128][LDP]  Kt[e][j] = k_j[e]
    float* Vs   = sm + 128*LDP;       // [128][LDP]  Vs[j][d]
    float* Qs   = sm + 2*128*LDP;     // Qt[e][i], later reused as S[i][j]
    float* wdec = sm + 3*128*LDP;     // [128] lambda^(127-j)

    const int c = blockIdx.x, h = blockIdx.y, b = blockIdx.z;
    const int tid = threadIdx.x;
    const int tx = tid & 15, ty = tid >> 4;
    const float sl = slope[h];
    if (tid < 128) wdec[tid] = expf(-sl * (float)(127 - tid));

    const float* base = g_qkv + ((size_t)(b*N_ + c*CH_)) * QKVS_ + h * (3*HD_);
#pragma unroll
    for (int it = 0; it < 16; it++) {
        int idx = tid + it*256;
        // Q,K: transpose to e-major (lanes vary along seq -> conflict-free STS)
        int seq = idx & 127;
        int e4  = (idx >> 7) << 2;
        const float* rp = base + (size_t)seq * QKVS_;
        float4 q4 = *(const float4*)(rp + e4);
        float4 k4 = *(const float4*)(rp + HD_ + e4);
        Qs[(e4+0)*LDP + seq] = q4.x;
        Qs[(e4+1)*LDP + seq] = q4.y;
        Qs[(e4+2)*LDP + seq] = q4.z;
        Qs[(e4+3)*LDP + seq] = q4.w;
        Kt[(e4+0)*LDP + seq] = k4.x;
        Kt[(e4+1)*LDP + seq] = k4.y;
        Kt[(e4+2)*LDP + seq] = k4.z;
        Kt[(e4+3)*LDP + seq] = k4.w;
        // V: natural j-major (coalesced GMEM, aligned float4 STS)
        int seq2 = idx >> 5;
        int d4   = (idx & 31) << 2;
        *(float4*)(Vs + seq2*LDP + d4) =
            *(const float4*)(base + (size_t)seq2 * QKVS_ + 2*HD_ + d4);
    }
    __syncthreads();

    // S = Q K^T (contract over e)
    float acc[8][8];
#pragma unroll
    for (int i = 0; i < 8; i++)
#pragma unroll
        for (int j = 0; j < 8; j++) acc[i][j] = 0.f;
    for (int e = 0; e < 128; e++) {
        float a[8], bb[8];
        *(float4*)&a[0]  = *(const float4*)&Qs[e*LDP + ty*8];
        *(float4*)&a[4]  = *(const float4*)&Qs[e*LDP + ty*8 + 4];
        *(float4*)&bb[0] = *(const float4*)&Kt[e*LDP + tx*8];
        *(float4*)&bb[4] = *(const float4*)&Kt[e*LDP + tx*8 + 4];
#pragma unroll
        for (int i = 0; i < 8; i++)
#pragma unroll
            for (int j = 0; j < 8; j++)
                acc[i][j] = fmaf(a[i], bb[j], acc[i][j]);
    }
    __syncthreads();   // all reads of Qs done; safe to overwrite with S

    // decay mask, store S naturally: Qs[i][j]
#pragma unroll
    for (int i = 0; i < 8; i++) {
        int ig = ty*8 + i;
        float tmp[8];
#pragma unroll
        for (int j = 0; j < 8; j++) {
            int jg = tx*8 + j;
            tmp[j] = (jg <= ig) ? acc[i][j] * expf(-sl * (float)(ig - jg)) : 0.f;
        }
        *(float4*)&Qs[ig*LDP + tx*8]     = *(float4*)&tmp[0];
        *(float4*)&Qs[ig*LDP + tx*8 + 4] = *(float4*)&tmp[4];
    }
    __syncthreads();

    // O_intra = S V  and  A = (wdec .* K)^T V   (both contract over j)
    float acco[8][8], acca[8][8];
#pragma unroll
    for (int i = 0; i < 8; i++)
#pragma unroll
        for (int j = 0; j < 8; j++) { acco[i][j] = 0.f; acca[i][j] = 0.f; }

    for (int j = 0; j < 128; j++) {
        float bb[8];
        *(float4*)&bb[0] = *(const float4*)&Vs[j*LDP + tx*8];
        *(float4*)&bb[4] = *(const float4*)&Vs[j*LDP + tx*8 + 4];
        float wj = wdec[j];
        float ao[8], aa[8];
#pragma unroll
        for (int i = 0; i < 8; i++) {
            ao[i] = Qs[(ty*8+i)*LDP + j];           // S[i][j] (broadcast)
            aa[i] = Kt[(ty*8+i)*LDP + j] * wj;      // K[j][e]*w[j] (broadcast)
        }
#pragma unroll
        for (int i = 0; i < 8; i++)
#pragma unroll
            for (int k = 0; k < 8; k++) {
                acco[i][k] = fmaf(ao[i], bb[k], acco[i][k]);
                acca[i][k] = fmaf(aa[i], bb[k], acca[i][k]);
            }
    }

#pragma unroll
    for (int i = 0; i < 8; i++) {
        int ig = ty*8 + i;
        float* op = g_O + ((size_t)(b*N_ + c*CH_ + ig)) * D_ + h*HD_ + tx*8;
        *(float4*)op       = *(float4*)&acco[i][0];
        *(float4*)(op + 4) = *(float4*)&acco[i][4];
        float* ap = g_A + ((((size_t)(b*H_ + h))*NC_ + c)*HD_ + ig)*HD_ + tx*8;
        *(float4*)ap       = *(float4*)&acca[i][0];
        *(float4*)(ap + 4) = *(float4*)&acca[i][4];
    }
}

// ---------------- phase 2: sequential chunk-state scan (cheap) ----------------
// KV_state(c) stored = state BEFORE chunk c; final state -> kv_final output
__global__ __launch_bounds__(256) void attn_phase2(
    const float* __restrict__ past_kv, const float* __restrict__ slope,
    float* __restrict__ kv_out, int write_kv)
{
    const int bh = blockIdx.x;
    const int h = bh & (H_ - 1);
    const int tid = threadIdx.x;
    const float lamC = expf(-slope[h] * (float)CH_);
    const size_t pb = (size_t)bh * (HD_*HD_);
    float st[64];
#pragma unroll
    for (int t = 0; t < 64; t++) st[t] = past_kv[pb + tid + t*256];
    for (int c = 0; c < NC_; c++) {
        const size_t kb = ((size_t)bh*NC_ + c) * (HD_*HD_);
#pragma unroll
        for (int t = 0; t < 64; t++) {
            g_KV[kb + tid + t*256] = st[t];
            st[t] = fmaf(lamC, st[t], g_A[kb + tid + t*256]);
        }
    }
    if (write_kv) {
#pragma unroll
        for (int t = 0; t < 64; t++) kv_out[pb + tid + t*256] = st[t];
    }
}

// ---------------- phase 3: inter-chunk O += lambda^(i+1) * Q KV0 ----------------
__global__ __launch_bounds__(256) void attn_phase3(const float* __restrict__ slope)
{
    extern __shared__ float sm[];
    float* Qs  = sm;               // Qt[e][i]
    float* KVs = sm + 128*LDP;     // KV[e][d]

    const int c = blockIdx.x, h = blockIdx.y, b = blockIdx.z;
    const int tid = threadIdx.x;
    const int tx = tid & 15, ty = tid >> 4;
    const float sl = slope[h];

    const float* qbase = g_qkv + ((size_t)(b*N_ + c*CH_)) * QKVS_ + h * (3*HD_);
    const float* kvbase = g_KV + (((size_t)(b*H_ + h))*NC_ + c) * (HD_*HD_);
#pragma unroll
    for (int it = 0; it < 16; it++) {
        int idx = tid + it*256;
        int seq = idx & 127;
        int e4  = (idx >> 7) << 2;
        float4 q4 = *(const float4*)(qbase + (size_t)seq * QKVS_ + e4);
        Qs[(e4+0)*LDP + seq] = q4.x;
        Qs[(e4+1)*LDP + seq] = q4.y;
        Qs[(e4+2)*LDP + seq] = q4.z;
        Qs[(e4+3)*LDP + seq] = q4.w;
        int er = idx >> 5;
        int d4 = (idx & 31) << 2;
        *(float4*)(KVs + er*LDP + d4) = *(const float4*)(kvbase + er*HD_ + d4);
    }
    __syncthreads();

    float acc[8][8];
#pragma unroll
    for (int i = 0; i < 8; i++)
#pragma unroll
        for (int j = 0; j < 8; j++) acc[i][j] = 0.f;
    for (int e = 0; e < 128; e++) {
        float a[8], bb[8];
        *(float4*)&a[0]  = *(const float4*)&Qs[e*LDP + ty*8];
        *(float4*)&a[4]  = *(const float4*)&Qs[e*LDP + ty*8 + 4];
        *(float4*)&bb[0] = *(const float4*)&KVs[e*LDP + tx*8];
        *(float4*)&bb[4] = *(const float4*)&KVs[e*LDP + tx*8 + 4];
#pragma unroll
        for (int i = 0; i < 8; i++)
#pragma unroll
            for (int j = 0; j < 8; j++)
                acc[i][j] = fmaf(a[i], bb[j], acc[i][j]);
    }

#pragma unroll
    for (int i = 0; i < 8; i++) {
        int ig = ty*8 + i;
        float sc = expf(-sl * (float)(ig + 1));
        float* op = g_O + ((size_t)(b*N_ + c*CH_ + ig)) * D_ + h*HD_ + tx*8;
        float4 c0 = *(float4*)op;
        float4 c1 = *(float4*)(op + 4);
        c0.x = fmaf(sc, acc[i][0], c0.x); c0.y = fmaf(sc, acc[i][1], c0.y);
        c0.z = fmaf(sc, acc[i][2], c0.z); c0.w = fmaf(sc, acc[i][3], c0.w);
        c1.x = fmaf(sc, acc[i][4], c1.x); c1.y = fmaf(sc, acc[i][5], c1.y);
        c1.z = fmaf(sc, acc[i][6], c1.z); c1.w = fmaf(sc, acc[i][7], c1.w);
        *(float4*)op       = c0;
        *(float4*)(op + 4) = c1;
    }
}

// ---------------- RMSNorm over h*hd, multiply by gate -> y (into g_gate) ----------------
__global__ __launch_bounds__(256) void rmsnorm_gate_k(const float* __restrict__ norm_w)
{
    const int row = blockIdx.x;
    const int tid = threadIdx.x;
    const float4* o4 = (const float4*)(g_O + (size_t)row * D_);
    float4* g4 = (float4*)(g_gate + (size_t)row * D_);
    const float4* w4 = (const float4*)norm_w;

    float4 v0 = o4[tid], v1 = o4[tid + 256];
    float s = v0.x*v0.x + v0.y*v0.y + v0.z*v0.z + v0.w*v0.w
            + v1.x*v1.x + v1.y*v1.y + v1.z*v1.z + v1.w*v1.w;
#pragma unroll
    for (int off = 16; off; off >>= 1) s += __shfl_xor_sync(0xffffffffu, s, off);
    __shared__ float red[8];
    if ((tid & 31) == 0) red[tid >> 5] = s;
    __syncthreads();
    float tot = red[0] + red[1] + red[2] + red[3] + red[4] + red[5] + red[6] + red[7];
    float r = rsqrtf(tot * (1.f / (float)D_) + 1e-6f);

    float4 gv0 = g4[tid], gv1 = g4[tid + 256];
    float4 w0 = w4[tid], w1 = w4[tid + 256];
    float4 y0, y1;
    y0.x = gv0.x * w0.x * v0.x * r; y0.y = gv0.y * w0.y * v0.y * r;
    y0.z = gv0.z * w0.z * v0.z * r; y0.w = gv0.w * w0.w * v0.w * r;
    y1.x = gv1.x * w1.x * v1.x * r; y1.y = gv1.y * w1.y * v1.y * r;
    y1.z = gv1.z * w1.z * v1.z * r; y1.w = gv1.w * w1.w * v1.w * r;
    g4[tid] = y0;
    g4[tid + 256] = y1;
}

// ---------------- launch ----------------
extern "C" void kernel_launch(void* const* d_in, const int* in_sizes, int n_in,
                              void* d_out, int out_size)
{
    const float* x       = (const float*)d_in[0];
    const float* past_kv = (const float*)d_in[1];
    const float* slope   = (const float*)d_in[2];
    const float* w_qkv   = (const float*)d_in[3];
    const float* w_gate  = (const float*)d_in[4];
    const float* w_out   = (const float*)d_in[5];
    const float* norm_w  = (const float*)d_in[6];
    float* out = (float*)d_out;

    float *qkv_p, *gate_p;
    cudaGetSymbolAddress((void**)&qkv_p, g_qkv);
    cudaGetSymbolAddress((void**)&gate_p, g_gate);

    const int P1_SMEM = (3*128*LDP + 128) * sizeof(float);
    const int P3_SMEM = (2*128*LDP) * sizeof(float);
    cudaFuncSetAttribute(attn_phase1, cudaFuncAttributeMaxDynamicSharedMemorySize, P1_SMEM);
    cudaFuncSetAttribute(attn_phase3, cudaFuncAttributeMaxDynamicSharedMemorySize, P3_SMEM);

    const int M = B_ * N_;   // 4096

    // 1. qkv = silu(x @ w_qkv^T)
    gemm_nt_act<<<dim3(QKVS_/128, M/128), 256>>>(x, w_qkv, qkv_p, M, QKVS_, D_, 1);
    // 2. gate = sigmoid(x @ w_gate^T)
    gemm_nt_act<<<dim3(D_/128, M/128), 256>>>(x, w_gate, gate_p, M, D_, D_, 2);
    // 3. per-chunk intra attention + KV summaries
    attn_phase1<<<dim3(NC_, H_, B_), 256, P1_SMEM>>>(slope);
    // 4. sequential chunk-state scan (+ kv_final to output tail if present)
    int write_kv = (out_size >= (int)(B_*N_*D_ + B_*H_*HD_*HD_)) ? 1 : 0;
    attn_phase2<<<B_*H_, 256>>>(past_kv, slope, out + (size_t)B_*N_*D_, write_kv);
    // 5. inter-chunk contribution
    attn_phase3<<<dim3(NC_, H_, B_), 256, P3_SMEM>>>(slope);
    // 6. RMSNorm * gate -> y (in g_gate)
    rmsnorm_gate_k<<<M, 256>>>(norm_w);
    // 7. out = y @ w_out^T
    gemm_nt_act<<<dim3(D_/128, M/128), 256>>>(gate_p, w_out, out, M, D_, D_, 0);
}

// round 3
// speedup vs baseline: 5.0841x; 5.0841x over previous
#include <cuda_runtime.h>
#include <cstdint>

#define B_ 2
#define N_ 2048
#define D_ 2048
#define H_ 16
#define HD_ 128
#define CH_ 128
#define NC_ (N_/CH_)          // 16
#define QKVS_ (3*H_*HD_)      // 6144
#define LDP 132               // padded smem stride for SIMT attention kernels

// -------- tensor-core GEMM config (shared by both paths) --------
#define BM 128
#define BN 128
#define BK 32                 // tf32 elems per K-stage = 128 bytes/row (SW128)
#define STAGES 4
#define STAGE_BYTES ((BM + BN) * BK * 4)     // 32768
#define SM_TC_TOTAL (1024 + STAGES * STAGE_BYTES)

// ---------------- scratch (static device allocations only) ----------------
__device__ float g_qkv[(size_t)B_ * N_ * QKVS_];
__device__ float g_gate[(size_t)B_ * N_ * D_];
__device__ float g_O[(size_t)B_ * N_ * D_];
__device__ float g_A[(size_t)B_ * H_ * NC_ * HD_ * HD_];
__device__ float g_KV[(size_t)B_ * H_ * NC_ * HD_ * HD_];
__device__ float g_xr[(size_t)B_ * N_ * D_];
__device__ float g_wq[(size_t)QKVS_ * D_];
__device__ float g_wg[(size_t)H_ * HD_ * D_];
__device__ float g_wo[(size_t)D_ * H_ * HD_];

// ---------------- helpers ----------------
__device__ __forceinline__ uint32_t smem_u32(const void* p) {
    uint32_t a;
    asm("{ .reg .u64 t; cvta.to.shared.u64 t, %1; cvt.u32.u64 %0, t; }" : "=r"(a) : "l"(p));
    return a;
}
__device__ __forceinline__ float to_tf32(float x) {
    uint32_t u;
    asm("cvt.rna.tf32.f32 %0, %1;" : "=r"(u) : "f"(x));
    return __uint_as_float(u);
}
__device__ __forceinline__ void cp_async16(uint32_t dst, const void* src) {
    asm volatile("cp.async.cg.shared.global [%0], [%1], 16;" :: "r"(dst), "l"(src));
}
__device__ __forceinline__ uint32_t lds_u32(uint32_t a) {
    uint32_t v;
    asm("ld.shared.b32 %0, [%1];" : "=r"(v) : "r"(a));
    return v;
}
__device__ __forceinline__ void mma16n8k8(float* c, const uint32_t* a, const uint32_t* b) {
    asm volatile("mma.sync.aligned.m16n8k8.row.col.f32.tf32.tf32.f32 "
                 "{%0,%1,%2,%3}, {%4,%5,%6,%7}, {%8,%9}, {%0,%1,%2,%3};"
                 : "+f"(c[0]), "+f"(c[1]), "+f"(c[2]), "+f"(c[3])
                 : "r"(a[0]), "r"(a[1]), "r"(a[2]), "r"(a[3]), "r"(b[0]), "r"(b[1]));
}
__device__ __forceinline__ float act_apply(float v, int act) {
    if (act == 1) return v / (1.f + __expf(-v));
    if (act == 2) return 1.f / (1.f + __expf(-v));
    return v;
}

#if defined(__CUDA_ARCH_FEAT_SM103_ALL)
// ---- tcgen05-only helpers (compiled only under sm_103a target) ----
__device__ __forceinline__ uint32_t elect1() {
    uint32_t p;
    asm volatile("{ .reg .pred p; elect.sync _|p, 0xFFFFFFFF; selp.b32 %0,1,0,p; }" : "=r"(p));
    return p;
}
__device__ __forceinline__ void mbar_init(uint32_t mbar, uint32_t cnt) {
    asm volatile("mbarrier.init.shared.b64 [%0], %1;" :: "r"(mbar), "r"(cnt) : "memory");
}
__device__ __forceinline__ void mbar_wait(uint32_t mbar, uint32_t parity) {
    uint32_t done;
    asm volatile("{ .reg .pred p; mbarrier.try_wait.parity.acquire.cta.shared::cta.b64 p, [%1], %2; selp.b32 %0,1,0,p; }"
                 : "=r"(done) : "r"(mbar), "r"(parity) : "memory");
    while (!done) {
        asm volatile("{ .reg .pred p; mbarrier.try_wait.parity.acquire.cta.shared::cta.b64 p, [%1], %2, 0x989680; selp.b32 %0,1,0,p; }"
                     : "=r"(done) : "r"(mbar), "r"(parity) : "memory");
    }
}
__device__ __forceinline__ void tc_commit(uint32_t mbar) {
    asm volatile("tcgen05.commit.cta_group::1.mbarrier::arrive::one.shared::cluster.b64 [%0];"
                 :: "r"(mbar) : "memory");
}
__device__ __forceinline__ void mma_tf32_ss(uint32_t d, uint64_t ad, uint64_t bd, uint32_t idesc, int acc) {
    uint32_t z = 0;
    asm volatile(
        "{\n\t.reg .pred p;\n\tsetp.ne.u32 p, %5, 0;\n\t"
        "tcgen05.mma.cta_group::1.kind::tf32 [%0], %1, %2, %3, {%4, %4, %4, %4}, p;\n\t}"
        :: "r"(d), "l"(ad), "l"(bd), "r"(idesc), "r"(z), "r"((uint32_t)acc) : "memory");
}
__device__ __forceinline__ uint64_t make_desc(uint32_t addr) {
    return ((uint64_t)2 << 61) | ((uint64_t)1 << 46) | ((uint64_t)64 << 32) | ((uint64_t)1 << 16)
         | ((uint64_t)(addr >> 4) & 0x3FFF);
}
#define IDESC_TF32 ((1u<<4) | (2u<<7) | (2u<<10) | ((BN/8)<<17) | ((BM/16)<<24))
#define TC_LD_X32(r, tmem_addr) \
    asm volatile( \
        "tcgen05.ld.sync.aligned.32x32b.x32.b32 " \
        "{%0, %1, %2, %3, %4, %5, %6, %7, " \
        " %8, %9, %10, %11, %12, %13, %14, %15, " \
        " %16, %17, %18, %19, %20, %21, %22, %23, " \
        " %24, %25, %26, %27, %28, %29, %30, %31}, [%32];" \
        : "=r"((r)[0]),  "=r"((r)[1]),  "=r"((r)[2]),  "=r"((r)[3]), \
          "=r"((r)[4]),  "=r"((r)[5]),  "=r"((r)[6]),  "=r"((r)[7]), \
          "=r"((r)[8]),  "=r"((r)[9]),  "=r"((r)[10]), "=r"((r)[11]), \
          "=r"((r)[12]), "=r"((r)[13]), "=r"((r)[14]), "=r"((r)[15]), \
          "=r"((r)[16]), "=r"((r)[17]), "=r"((r)[18]), "=r"((r)[19]), \
          "=r"((r)[20]), "=r"((r)[21]), "=r"((r)[22]), "=r"((r)[23]), \
          "=r"((r)[24]), "=r"((r)[25]), "=r"((r)[26]), "=r"((r)[27]), \
          "=r"((r)[28]), "=r"((r)[29]), "=r"((r)[30]), "=r"((r)[31]) \
        : "r"(tmem_addr))
#endif

// ---------------- tf32 rounding pass ----------------
__global__ __launch_bounds__(256) void round_tf32_k(const float4* __restrict__ in,
                                                    float4* __restrict__ out, int n4)
{
    int i = blockIdx.x * 256 + threadIdx.x;
    int stride = gridDim.x * 256;
    for (; i < n4; i += stride) {
        float4 v = in[i];
        v.x = to_tf32(v.x); v.y = to_tf32(v.y); v.z = to_tf32(v.z); v.w = to_tf32(v.w);
        out[i] = v;
    }
}

// ---------------- tensor-core tf32 GEMM: C = act(A @ B^T) ----------------
// A: [M,K] row-major tf32-rounded, B: [Nn,K] row-major tf32-rounded, C: [M,Nn] fp32
__global__ __launch_bounds__(256) void gemm_tc(
    const float* __restrict__ A, const float* __restrict__ Bm,
    float* __restrict__ C, int M, int Nn, int K, int act)
{
    extern __shared__ char smem[];
    const uint32_t sbase = smem_u32(smem);
    const int tid = threadIdx.x;
    const int bm = blockIdx.y * BM, bn = blockIdx.x * BN;
    const int NK = K / BK;
    const int row8 = tid >> 3, seg = tid & 7;

    // stage loader: A and B each 128 rows x 128 bytes, SW128-swizzled
    auto load_stage = [&](int s, int kidx) {
        uint32_t a_s = sbase + 1024 + s * STAGE_BYTES;
        uint32_t b_s = a_s + BM * BK * 4;
        const float* ag = A + (size_t)bm * K + kidx * BK + seg * 4;
        const float* bg = Bm + (size_t)bn * K + kidx * BK + seg * 4;
#pragma unroll
        for (int i = 0; i < 4; i++) {
            int r = row8 + i * 32;
            uint32_t off = r * 128 + seg * 16;
            uint32_t sw = off ^ ((off >> 3) & 0x70);
            cp_async16(a_s + sw, ag + (size_t)r * K);
            cp_async16(b_s + sw, bg + (size_t)r * K);
        }
        asm volatile("cp.async.commit_group;" ::: "memory");
    };
    // tail-correct wait: ensure group for stage ks is complete
    auto wait_for = [&](int ks) {
        if (ks + 3 <= NK)      asm volatile("cp.async.wait_group 2;" ::: "memory");
        else if (ks + 2 == NK) asm volatile("cp.async.wait_group 1;" ::: "memory");
        else                   asm volatile("cp.async.wait_group 0;" ::: "memory");
    };

#if defined(__CUDA_ARCH_FEAT_SM103_ALL)
    // ================= tcgen05 path =================
    const int wid = tid >> 5, lane = tid & 31;
    const uint32_t SM_TM = sbase;
    const uint32_t SM_MBAR = sbase + 16;
    if (wid == 0) {
        asm volatile("tcgen05.alloc.cta_group::1.sync.aligned.shared::cta.b32 [%0], %1;"
                     :: "r"(SM_TM), "r"(128) : "memory");
        asm volatile("tcgen05.relinquish_alloc_permit.cta_group::1.sync.aligned;");
    }
    if (tid == 0) {
        for (int s = 0; s < STAGES; s++) mbar_init(SM_MBAR + s * 8, 1);
    }
    __syncthreads();
    uint32_t tmem;
    asm volatile("ld.shared.b32 %0, [%1];" : "=r"(tmem) : "r"(SM_TM));

    load_stage(0, 0); load_stage(1, 1); load_stage(2, 2);

    for (int ks = 0; ks < NK; ks++) {
        const int buf = ks & (STAGES - 1);
        wait_for(ks);
        __syncthreads();
        if (wid == 0) {
            asm volatile("fence.proxy.async.shared::cta;" ::: "memory");
            if (elect1()) {
                uint32_t a_s = sbase + 1024 + buf * STAGE_BYTES;
                uint64_t ad = make_desc(a_s);
                uint64_t bd = make_desc(a_s + BM * BK * 4);
#pragma unroll
                for (int k = 0; k < 4; k++)
                    mma_tf32_ss(tmem, ad + k * 2, bd + k * 2, IDESC_TF32, (ks > 0) || (k > 0));
                tc_commit(SM_MBAR + buf * 8);
            }
        }
        const int nk2 = ks + STAGES - 1;
        if (nk2 < NK) {
            const int buf2 = nk2 & (STAGES - 1);
            if (ks >= 1) mbar_wait(SM_MBAR + buf2 * 8, ((ks - 1) >> 2) & 1);
            load_stage(buf2, nk2);
        }
    }
    mbar_wait(SM_MBAR + ((NK - 1) & (STAGES - 1)) * 8, ((NK - 1) >> 2) & 1);
    asm volatile("tcgen05.fence::after_thread_sync;" ::: "memory");

    // epilogue: warps 0-3 cols 0-63, warps 4-7 cols 64-127; rows by (wid&3)
    {
        const int row = bm + (wid & 3) * 32 + lane;
        const int colb = (wid >> 2) * 64;
        float* cbase = C + (size_t)row * Nn + bn + colb;
#pragma unroll
        for (int c0 = 0; c0 < 64; c0 += 32) {
            uint32_t r[32];
            TC_LD_X32(r, tmem + colb + c0);
            asm volatile("tcgen05.wait::ld.sync.aligned;" ::: "memory");
#pragma unroll
            for (int q = 0; q < 8; q++) {
                float4 v;
                v.x = act_apply(__uint_as_float(r[q*4+0]), act);
                v.y = act_apply(__uint_as_float(r[q*4+1]), act);
                v.z = act_apply(__uint_as_float(r[q*4+2]), act);
                v.w = act_apply(__uint_as_float(r[q*4+3]), act);
                *(float4*)(cbase + c0 + q * 4) = v;
            }
        }
    }
    __syncthreads();
    if (wid == 0) {
        asm volatile("tcgen05.dealloc.cta_group::1.sync.aligned.b32 %0, %1;" :: "r"(tmem), "r"(128));
    }
#else
    // ================= mma.sync (HMMA tf32) path =================
    const int lane = tid & 31, w = tid >> 5;
    const int wm = (w >> 2) * 64;        // warp grid 2 (m) x 4 (n)
    const int wn = (w & 3) * 32;
    const int tr = lane >> 2, tc = lane & 3;
    const uint32_t trm = (uint32_t)tr << 4;   // swizzle mask, constant per thread

    float acc[4][4][4];
#pragma unroll
    for (int i = 0; i < 4; i++)
#pragma unroll
        for (int j = 0; j < 4; j++)
#pragma unroll
            for (int q = 0; q < 4; q++) acc[i][j][q] = 0.f;

    load_stage(0, 0); load_stage(1, 1); load_stage(2, 2);

    for (int ks = 0; ks < NK; ks++) {
        const int buf = ks & (STAGES - 1);
        wait_for(ks);
        __syncthreads();
        const int nk2 = ks + STAGES - 1;
        if (nk2 < NK) load_stage(nk2 & (STAGES - 1), nk2);

        const uint32_t a_s = sbase + 1024 + buf * STAGE_BYTES;
        const uint32_t b_s = a_s + BM * BK * 4;
        const uint32_t aT = a_s + (uint32_t)(wm + tr) * 128;
        const uint32_t bT = b_s + (uint32_t)(wn + tr) * 128;

#pragma unroll
        for (int ksl = 0; ksl < 4; ksl++) {
            const uint32_t cb = (uint32_t)(ksl * 32 + tc * 4);
            const uint32_t cA = cb ^ trm;
            const uint32_t cB = (cb + 16) ^ trm;
            uint32_t av[4][4];
#pragma unroll
            for (int i = 0; i < 4; i++) {
                uint32_t rb = aT + i * 2048;
                av[i][0] = lds_u32(rb + cA);
                av[i][1] = lds_u32(rb + 1024 + cA);
                av[i][2] = lds_u32(rb + cB);
                av[i][3] = lds_u32(rb + 1024 + cB);
            }
            uint32_t bv[4][2];
#pragma unroll
            for (int j = 0; j < 4; j++) {
                uint32_t nb = bT + j * 1024;
                bv[j][0] = lds_u32(nb + cA);
                bv[j][1] = lds_u32(nb + cB);
            }
#pragma unroll
            for (int i = 0; i < 4; i++)
#pragma unroll
                for (int j = 0; j < 4; j++)
                    mma16n8k8(acc[i][j], av[i], bv[j]);
        }
    }

    // epilogue
#pragma unroll
    for (int i = 0; i < 4; i++) {
#pragma unroll
        for (int j = 0; j < 4; j++) {
            int r0 = bm + wm + i * 16 + tr;
            int c0 = bn + wn + j * 8 + 2 * tc;
            float2 v0, v1;
            v0.x = act_apply(acc[i][j][0], act);
            v0.y = act_apply(acc[i][j][1], act);
            v1.x = act_apply(acc[i][j][2], act);
            v1.y = act_apply(acc[i][j][3], act);
            *(float2*)(C + (size_t)r0 * Nn + c0) = v0;
            *(float2*)(C + (size_t)(r0 + 8) * Nn + c0) = v1;
        }
    }
#endif
}

// ---------------- phase 1: per-chunk intra attention + KV summary ----------------
__global__ __launch_bounds__(256) void attn_phase1(const float* __restrict__ slope)
{
    extern __shared__ float sm[];
    float* Kt   = sm;
    float* Vs   = sm + 128*LDP;
    float* Qs   = sm + 2*128*LDP;
    float* wdec = sm + 3*128*LDP;   // wdec[j] = e^{-sl*(127-j)}; lamp[t] = wdec[127-t]

    const int c = blockIdx.x, h = blockIdx.y, b = blockIdx.z;
    const int tid = threadIdx.x;
    const int tx = tid & 15, ty = tid >> 4;
    const float sl = slope[h];
    if (tid < 128) wdec[tid] = __expf(-sl * (float)(127 - tid));

    const float* base = g_qkv + ((size_t)(b*N_ + c*CH_)) * QKVS_ + h * (3*HD_);
#pragma unroll
    for (int it = 0; it < 16; it++) {
        int idx = tid + it*256;
        int seq = idx & 127;
        int e4  = (idx >> 7) << 2;
        const float* rp = base + (size_t)seq * QKVS_;
        float4 q4 = *(const float4*)(rp + e4);
        float4 k4 = *(const float4*)(rp + HD_ + e4);
        Qs[(e4+0)*LDP + seq] = q4.x;
        Qs[(e4+1)*LDP + seq] = q4.y;
        Qs[(e4+2)*LDP + seq] = q4.z;
        Qs[(e4+3)*LDP + seq] = q4.w;
        Kt[(e4+0)*LDP + seq] = k4.x;
        Kt[(e4+1)*LDP + seq] = k4.y;
        Kt[(e4+2)*LDP + seq] = k4.z;
        Kt[(e4+3)*LDP + seq] = k4.w;
        int seq2 = idx >> 5;
        int d4   = (idx & 31) << 2;
        *(float4*)(Vs + seq2*LDP + d4) =
            *(const float4*)(base + (size_t)seq2 * QKVS_ + 2*HD_ + d4);
    }
    __syncthreads();

    float acc[8][8];
#pragma unroll
    for (int i = 0; i < 8; i++)
#pragma unroll
        for (int j = 0; j < 8; j++) acc[i][j] = 0.f;
    for (int e = 0; e < 128; e++) {
        float a[8], bb[8];
        *(float4*)&a[0]  = *(const float4*)&Qs[e*LDP + ty*8];
        *(float4*)&a[4]  = *(const float4*)&Qs[e*LDP + ty*8 + 4];
        *(float4*)&bb[0] = *(const float4*)&Kt[e*LDP + tx*8];
        *(float4*)&bb[4] = *(const float4*)&Kt[e*LDP + tx*8 + 4];
#pragma unroll
        for (int i = 0; i < 8; i++)
#pragma unroll
            for (int j = 0; j < 8; j++)
                acc[i][j] = fmaf(a[i], bb[j], acc[i][j]);
    }
    __syncthreads();

#pragma unroll
    for (int i = 0; i < 8; i++) {
        int ig = ty*8 + i;
        float tmp[8];
#pragma unroll
        for (int j = 0; j < 8; j++) {
            int jg = tx*8 + j;
            tmp[j] = (jg <= ig) ? acc[i][j] * wdec[127 - (ig - jg)] : 0.f;
        }
        *(float4*)&Qs[ig*LDP + tx*8]     = *(float4*)&tmp[0];
        *(float4*)&Qs[ig*LDP + tx*8 + 4] = *(float4*)&tmp[4];
    }
    __syncthreads();

    float acco[8][8], acca[8][8];
#pragma unroll
    for (int i = 0; i < 8; i++)
#pragma unroll
        for (int j = 0; j < 8; j++) { acco[i][j] = 0.f; acca[i][j] = 0.f; }

    for (int j = 0; j < 128; j++) {
        float bb[8];
        *(float4*)&bb[0] = *(const float4*)&Vs[j*LDP + tx*8];
        *(float4*)&bb[4] = *(const float4*)&Vs[j*LDP + tx*8 + 4];
        float wj = wdec[j];
        float ao[8], aa[8];
#pragma unroll
        for (int i = 0; i < 8; i++) {
            ao[i] = Qs[(ty*8+i)*LDP + j];
            aa[i] = Kt[(ty*8+i)*LDP + j] * wj;
        }
#pragma unroll
        for (int i = 0; i < 8; i++)
#pragma unroll
            for (int k = 0; k < 8; k++) {
                acco[i][k] = fmaf(ao[i], bb[k], acco[i][k]);
                acca[i][k] = fmaf(aa[i], bb[k], acca[i][k]);
            }
    }

#pragma unroll
    for (int i = 0; i < 8; i++) {
        int ig = ty*8 + i;
        float* op = g_O + ((size_t)(b*N_ + c*CH_ + ig)) * D_ + h*HD_ + tx*8;
        *(float4*)op       = *(float4*)&acco[i][0];
        *(float4*)(op + 4) = *(float4*)&acco[i][4];
        float* ap = g_A + ((((size_t)(b*H_ + h))*NC_ + c)*HD_ + ig)*HD_ + tx*8;
        *(float4*)ap       = *(float4*)&acca[i][0];
        *(float4*)(ap + 4) = *(float4*)&acca[i][4];
    }
}

// ---------------- phase 2: chunk-state scan, elementwise-parallel ----------------
__global__ __launch_bounds__(256) void attn_phase2(
    const float* __restrict__ past_kv, const float* __restrict__ slope,
    float* __restrict__ kv_out, int write_kv)
{
    const int bh = blockIdx.x;
    const int h = bh & (H_ - 1);
    const int tid = threadIdx.x;
    const float lamC = __expf(-slope[h] * (float)CH_);
    const size_t eb = (size_t)blockIdx.y * 2048 + tid;
    const size_t pb = (size_t)bh * (HD_*HD_);
    float st[8];
#pragma unroll
    for (int t = 0; t < 8; t++) st[t] = past_kv[pb + eb + t*256];
    for (int c = 0; c < NC_; c++) {
        const size_t kb = ((size_t)bh*NC_ + c) * (HD_*HD_);
#pragma unroll
        for (int t = 0; t < 8; t++) {
            g_KV[kb + eb + t*256] = st[t];
            st[t] = fmaf(lamC, st[t], g_A[kb + eb + t*256]);
        }
    }
    if (write_kv) {
#pragma unroll
        for (int t = 0; t < 8; t++) kv_out[pb + eb + t*256] = st[t];
    }
}

// ---------------- phase 3: inter-chunk O += lambda^(i+1) * Q KV0 ----------------
__global__ __launch_bounds__(256) void attn_phase3(const float* __restrict__ slope)
{
    extern __shared__ float sm[];
    float* Qs  = sm;
    float* KVs = sm + 128*LDP;

    const int c = blockIdx.x, h = blockIdx.y, b = blockIdx.z;
    const int tid = threadIdx.x;
    const int tx = tid & 15, ty = tid >> 4;
    const float sl = slope[h];

    const float* qbase = g_qkv + ((size_t)(b*N_ + c*CH_)) * QKVS_ + h * (3*HD_);
    const float* kvbase = g_KV + (((size_t)(b*H_ + h))*NC_ + c) * (HD_*HD_);
#pragma unroll
    for (int it = 0; it < 16; it++) {
        int idx = tid + it*256;
        int seq = idx & 127;
        int e4  = (idx >> 7) << 2;
        float4 q4 = *(const float4*)(qbase + (size_t)seq * QKVS_ + e4);
        Qs[(e4+0)*LDP + seq] = q4.x;
        Qs[(e4+1)*LDP + seq] = q4.y;
        Qs[(e4+2)*LDP + seq] = q4.z;
        Qs[(e4+3)*LDP + seq] = q4.w;
        int er = idx >> 5;
        int d4 = (idx & 31) << 2;
        *(float4*)(KVs + er*LDP + d4) = *(const float4*)(kvbase + er*HD_ + d4);
    }
    __syncthreads();

    float acc[8][8];
#pragma unroll
    for (int i = 0; i < 8; i++)
#pragma unroll
        for (int j = 0; j < 8; j++) acc[i][j] = 0.f;
    for (int e = 0; e < 128; e++) {
        float a[8], bb[8];
        *(float4*)&a[0]  = *(const float4*)&Qs[e*LDP + ty*8];
        *(float4*)&a[4]  = *(const float4*)&Qs[e*LDP + ty*8 + 4];
        *(float4*)&bb[0] = *(const float4*)&KVs[e*LDP + tx*8];
        *(float4*)&bb[4] = *(const float4*)&KVs[e*LDP + tx*8 + 4];
#pragma unroll
        for (int i = 0; i < 8; i++)
#pragma unroll
            for (int j = 0; j < 8; j++)
                acc[i][j] = fmaf(a[i], bb[j], acc[i][j]);
    }

#pragma unroll
    for (int i = 0; i < 8; i++) {
        int ig = ty*8 + i;
        float sc = __expf(-sl * (float)(ig + 1));
        float* op = g_O + ((size_t)(b*N_ + c*CH_ + ig)) * D_ + h*HD_ + tx*8;
        float4 c0 = *(float4*)op;
        float4 c1 = *(float4*)(op + 4);
        c0.x = fmaf(sc, acc[i][0], c0.x); c0.y = fmaf(sc, acc[i][1], c0.y);
        c0.z = fmaf(sc, acc[i][2], c0.z); c0.w = fmaf(sc, acc[i][3], c0.w);
        c1.x = fmaf(sc, acc[i][4], c1.x); c1.y = fmaf(sc, acc[i][5], c1.y);
        c1.z = fmaf(sc, acc[i][6], c1.z); c1.w = fmaf(sc, acc[i][7], c1.w);
        *(float4*)op       = c0;
        *(float4*)(op + 4) = c1;
    }
}

// ---------------- RMSNorm * gate -> y (tf32-rounded, into g_gate) ----------------
__global__ __launch_bounds__(256) void rmsnorm_gate_k(const float* __restrict__ norm_w)
{
    const int row = blockIdx.x;
    const int tid = threadIdx.x;
    const float4* o4 = (const float4*)(g_O + (size_t)row * D_);
    float4* g4 = (float4*)(g_gate + (size_t)row * D_);
    const float4* w4 = (const float4*)norm_w;

    float4 v0 = o4[tid], v1 = o4[tid + 256];
    float s = v0.x*v0.x + v0.y*v0.y + v0.z*v0.z + v0.w*v0.w
            + v1.x*v1.x + v1.y*v1.y + v1.z*v1.z + v1.w*v1.w;
#pragma unroll
    for (int off = 16; off; off >>= 1) s += __shfl_xor_sync(0xffffffffu, s, off);
    __shared__ float red[8];
    if ((tid & 31) == 0) red[tid >> 5] = s;
    __syncthreads();
    float tot = red[0] + red[1] + red[2] + red[3] + red[4] + red[5] + red[6] + red[7];
    float r = rsqrtf(tot * (1.f / (float)D_) + 1e-6f);

    float4 gv0 = g4[tid], gv1 = g4[tid + 256];
    float4 w0 = w4[tid], w1 = w4[tid + 256];
    float4 y0, y1;
    y0.x = to_tf32(gv0.x * w0.x * v0.x * r); y0.y = to_tf32(gv0.y * w0.y * v0.y * r);
    y0.z = to_tf32(gv0.z * w0.z * v0.z * r); y0.w = to_tf32(gv0.w * w0.w * v0.w * r);
    y1.x = to_tf32(gv1.x * w1.x * v1.x * r); y1.y = to_tf32(gv1.y * w1.y * v1.y * r);
    y1.z = to_tf32(gv1.z * w1.z * v1.z * r); y1.w = to_tf32(gv1.w * w1.w * v1.w * r);
    g4[tid] = y0;
    g4[tid + 256] = y1;
}

// ---------------- launch ----------------
extern "C" void kernel_launch(void* const* d_in, const int* in_sizes, int n_in,
                              void* d_out, int out_size)
{
    const float* x       = (const float*)d_in[0];
    const float* past_kv = (const float*)d_in[1];
    const float* slope   = (const float*)d_in[2];
    const float* w_qkv   = (const float*)d_in[3];
    const float* w_gate  = (const float*)d_in[4];
    const float* w_out   = (const float*)d_in[5];
    const float* norm_w  = (const float*)d_in[6];
    float* out = (float*)d_out;

    float *qkv_p, *gate_p, *xr_p, *wq_p, *wg_p, *wo_p;
    cudaGetSymbolAddress((void**)&qkv_p, g_qkv);
    cudaGetSymbolAddress((void**)&gate_p, g_gate);
    cudaGetSymbolAddress((void**)&xr_p, g_xr);
    cudaGetSymbolAddress((void**)&wq_p, g_wq);
    cudaGetSymbolAddress((void**)&wg_p, g_wg);
    cudaGetSymbolAddress((void**)&wo_p, g_wo);

    const int P1_SMEM = (3*128*LDP + 128) * sizeof(float);
    const int P3_SMEM = (2*128*LDP) * sizeof(float);
    cudaFuncSetAttribute(attn_phase1, cudaFuncAttributeMaxDynamicSharedMemorySize, P1_SMEM);
    cudaFuncSetAttribute(attn_phase3, cudaFuncAttributeMaxDynamicSharedMemorySize, P3_SMEM);
    cudaFuncSetAttribute(gemm_tc, cudaFuncAttributeMaxDynamicSharedMemorySize, SM_TC_TOTAL);

    const int M = B_ * N_;   // 4096

    // tf32 pre-rounding (round-to-nearest, unbiased)
    round_tf32_k<<<1024, 256>>>((const float4*)x, (float4*)xr_p, (B_*N_*D_)/4);
    round_tf32_k<<<1024, 256>>>((const float4*)w_qkv, (float4*)wq_p, (QKVS_*D_)/4);
    round_tf32_k<<<1024, 256>>>((const float4*)w_gate, (float4*)wg_p, (H_*HD_*D_)/4);
    round_tf32_k<<<1024, 256>>>((const float4*)w_out, (float4*)wo_p, (D_*H_*HD_)/4);

    // 1. qkv = silu(x @ w_qkv^T)
    gemm_tc<<<dim3(QKVS_/BN, M/BM), 256, SM_TC_TOTAL>>>(xr_p, wq_p, qkv_p, M, QKVS_, D_, 1);
    // 2. gate = sigmoid(x @ w_gate^T)
    gemm_tc<<<dim3(D_/BN, M/BM), 256, SM_TC_TOTAL>>>(xr_p, wg_p, gate_p, M, D_, D_, 2);
    // 3. per-chunk intra attention + KV summaries
    attn_phase1<<<dim3(NC_, H_, B_), 256, P1_SMEM>>>(slope);
    // 4. chunk-state scan
    int write_kv = (out_size >= (int)(B_*N_*D_ + B_*H_*HD_*HD_)) ? 1 : 0;
    attn_phase2<<<dim3(B_*H_, 8), 256>>>(past_kv, slope, out + (size_t)B_*N_*D_, write_kv);
    // 5. inter-chunk contribution
    attn_phase3<<<dim3(NC_, H_, B_), 256, P3_SMEM>>>(slope);
    // 6. RMSNorm * gate -> y
    rmsnorm_gate_k<<<M, 256>>>(norm_w);
    // 7. out = y @ w_out^T
    gemm_tc<<<dim3(D_/BN, M/BM), 256, SM_TC_TOTAL>>>(gate_p, wo_p, out, M, D_, D_, 0);
}